// round 2
// baseline (speedup 1.0000x reference)
#include <cuda_runtime.h>

#define ULL unsigned long long

// ---------- packed f32x2 helpers (sm_100+/sm_103a) ----------
__device__ __forceinline__ ULL pack2(float a, float b) {
    ULL r; asm("mov.b64 %0, {%1,%2};" : "=l"(r) : "f"(a), "f"(b)); return r;
}
__device__ __forceinline__ float2 unpack2(ULL p) {
    float2 f; asm("mov.b64 {%0,%1}, %2;" : "=f"(f.x), "=f"(f.y) : "l"(p)); return f;
}
__device__ __forceinline__ void fma2(ULL& d, ULL a, ULL b) {
    asm("fma.rn.f32x2 %0, %1, %2, %0;" : "+l"(d) : "l"(a), "l"(b));
}

__device__ __forceinline__ float gelu_exact(float x) {
    return 0.5f * x * (1.0f + erff(x * 0.70710678118654752440f));
}

// ---------- scratch (static device globals; no runtime allocation) ----------
__device__ float g_x[4 * 65536 * 32];      // tokens after conv+concat (shortcut 1)
__device__ float g_qkv[4 * 65536 * 96];    // q (pre-scaled) | k | v per token
__device__ float g_x2[4 * 65536 * 32];     // x + attn(proj) (shortcut 2)

// ============================================================================
// K1: 3x3 SAME conv, Cin=128 -> Co=16, applied to both inputs, written as
// tokens [b][l][32] with channels 0-15 = conv(image), 16-31 = conv(event).
// Tile: 64x16 output pixels per 256-thread CTA; thread = 4 adjacent-x pixels
// (2 f32x2 pairs) x 16 output channels.  Weights pre-splatted in smem.
// ============================================================================
__global__ __launch_bounds__(256, 2) void conv_kernel(
    const float* __restrict__ img, const float* __restrict__ evt,
    const float* __restrict__ cw, const float* __restrict__ cb)
{
    __shared__ float sIn[8][18][68];     // [ic][row][col], pitch 68
    __shared__ ULL   sW2[8 * 9 * 16];    // [(ic*9+tap)*16 + oc], (w,w) pairs

    const int t     = threadIdx.x;
    const int xbase = blockIdx.x * 64;
    const int ybase = blockIdx.y * 16;
    const int b     = blockIdx.z >> 1;
    const int half  = blockIdx.z & 1;
    const float* __restrict__ src = (half ? evt : img) + (size_t)b * 128 * 65536;

    const int lx0 = (t & 15) * 4;
    const int ly  = t >> 4;

    ULL acc[16][2];
#pragma unroll
    for (int oc = 0; oc < 16; oc++) { acc[oc][0] = 0ULL; acc[oc][1] = 0ULL; }

    for (int ic0 = 0; ic0 < 128; ic0 += 8) {
        __syncthreads();
        // stage weights (duplicated into both f32x2 lanes)
        for (int i = t; i < 8 * 9 * 16; i += 256) {
            int oc = i & 15;
            int r  = i >> 4;                 // r = ic*9 + tap
            float wv = cw[(oc * 128 + ic0 + (r / 9)) * 9 + (r % 9)];
            unsigned u = __float_as_uint(wv);
            sW2[i] = ((ULL)u << 32) | u;
        }
        // stage input tile (with halo, zero-padded at image border)
        for (int i = t; i < 8 * 18 * 66; i += 256) {
            int icc = i / (18 * 66);
            int r2  = i - icc * (18 * 66);
            int rr  = r2 / 66;
            int cc  = r2 - rr * 66;
            int gy  = ybase - 1 + rr;
            int gx  = xbase - 1 + cc;
            float v = 0.f;
            if ((unsigned)gy < 256u && (unsigned)gx < 256u)
                v = src[((ic0 + icc) * 256 + gy) * 256 + gx];
            sIn[icc][rr][cc] = v;
        }
        __syncthreads();

#pragma unroll 2
        for (int icc = 0; icc < 8; icc++) {
#pragma unroll
            for (int dy = 0; dy < 3; dy++) {
                const float* row = &sIn[icc][ly + dy][lx0];
                float4 v03 = *(const float4*)row;        // 16B aligned
                float2 v45 = *(const float2*)(row + 4);  //  8B aligned
                ULL A[3], Bv[3];
                A[0]  = pack2(v03.x, v03.y);
                A[1]  = pack2(v03.y, v03.z);
                A[2]  = pack2(v03.z, v03.w);
                Bv[0] = A[2];
                Bv[1] = pack2(v03.w, v45.x);
                Bv[2] = pack2(v45.x, v45.y);
                const ULL* wr = &sW2[(icc * 9 + dy * 3) * 16];
#pragma unroll
                for (int dx = 0; dx < 3; dx++) {
#pragma unroll
                    for (int oc = 0; oc < 16; oc++) {
                        ULL wv = wr[dx * 16 + oc];
                        fma2(acc[oc][0], A[dx],  wv);
                        fma2(acc[oc][1], Bv[dx], wv);
                    }
                }
            }
        }
    }

    float bias[16];
#pragma unroll
    for (int oc = 0; oc < 16; oc++) bias[oc] = cb[oc];
    const int gy = ybase + ly;
    const size_t tokbase = (size_t)b * 65536 + (size_t)gy * 256 + xbase + lx0;
#pragma unroll
    for (int p = 0; p < 2; p++) {
        float v0[16], v1[16];
#pragma unroll
        for (int oc = 0; oc < 16; oc++) {
            float2 f = unpack2(acc[oc][p]);
            v0[oc] = f.x + bias[oc];
            v1[oc] = f.y + bias[oc];
        }
        float4* d0 = (float4*)&g_x[(tokbase + 2 * p)     * 32 + half * 16];
        float4* d1 = (float4*)&g_x[(tokbase + 2 * p + 1) * 32 + half * 16];
#pragma unroll
        for (int q = 0; q < 4; q++) {
            d0[q] = make_float4(v0[4*q], v0[4*q+1], v0[4*q+2], v0[4*q+3]);
            d1[q] = make_float4(v1[4*q], v1[4*q+1], v1[4*q+2], v1[4*q+3]);
        }
    }
}

// ============================================================================
// K2: LayerNorm(D=32) + QKV projection (32 -> 96), q pre-scaled by 8^-0.5.
// One token per thread; f32x2 pairs over adjacent output channels j.
// ============================================================================
__global__ __launch_bounds__(256) void lnqkv_kernel(
    const float* __restrict__ g1, const float* __restrict__ b1,
    const float* __restrict__ qw, const float* __restrict__ qb)
{
    __shared__ ULL   w2[32 * 48];   // [d][jpair]: (w[2jp][d], w[2jp+1][d])
    __shared__ float sg[32], sb[32], sqb[96];
    const int t = threadIdx.x;
    for (int i = t; i < 32 * 48; i += 256) {
        int d = i / 48, jp = i - (i / 48) * 48;
        unsigned ua = __float_as_uint(qw[(2 * jp)     * 32 + d]);
        unsigned ub = __float_as_uint(qw[(2 * jp + 1) * 32 + d]);
        w2[i] = ((ULL)ub << 32) | ua;
    }
    if (t < 32) { sg[t] = g1[t]; sb[t] = b1[t]; }
    if (t < 96) sqb[t] = qb[t];
    __syncthreads();

    const size_t tok = (size_t)blockIdx.x * 256 + t;
    float y[32];
    const float4* xp = (const float4*)&g_x[tok * 32];
#pragma unroll
    for (int q = 0; q < 8; q++) {
        float4 f = xp[q];
        y[4*q] = f.x; y[4*q+1] = f.y; y[4*q+2] = f.z; y[4*q+3] = f.w;
    }
    float s = 0.f;
#pragma unroll
    for (int d = 0; d < 32; d++) s += y[d];
    float mu = s * (1.f / 32.f);
    float var = 0.f;
#pragma unroll
    for (int d = 0; d < 32; d++) { float dd = y[d] - mu; var += dd * dd; }
    float rs = rsqrtf(var * (1.f / 32.f) + 1e-5f);
#pragma unroll
    for (int d = 0; d < 32; d++) y[d] = (y[d] - mu) * rs * sg[d] + sb[d];

    const float scaleq = 0.35355339059327373f;  // (D/heads)^-0.5 = 8^-0.5
    for (int jc = 0; jc < 4; jc++) {
        ULL a2[12];
#pragma unroll
        for (int p = 0; p < 12; p++) a2[p] = 0ULL;
        for (int d = 0; d < 32; d++) {
            ULL y2 = pack2(y[d], y[d]);
            const ULL* wr = &w2[d * 48 + jc * 12];
#pragma unroll
            for (int p = 0; p < 12; p++) fma2(a2[p], y2, wr[p]);
        }
#pragma unroll
        for (int p = 0; p < 12; p++) {
            int j = (jc * 12 + p) * 2;
            float2 f = unpack2(a2[p]);
            f.x += sqb[j]; f.y += sqb[j + 1];
            if (j < 32) { f.x *= scaleq; f.y *= scaleq; }   // pair never straddles q/k boundary
            *(float2*)&g_qkv[tok * 96 + j] = f;
        }
    }
}

// ============================================================================
// K3: windowed attention (8x8 windows, 4 heads, hd=8) + rel-pos bias +
// softmax + AV + output projection + residual.  One CTA per window; thread =
// one (head, query) row; m-dimension processed as f32x2 pairs from transposed
// K/V smem tiles.
// ============================================================================
__global__ __launch_bounds__(256, 2) void attn_kernel(
    const float* __restrict__ rpb, const float* __restrict__ pw,
    const float* __restrict__ pb)
{
    __shared__ float q_s[4 * 64 * 8];   // [head][n][c]
    __shared__ float kT[4 * 8 * 64];    // [head][c][m]
    __shared__ float vT[4 * 8 * 64];    // [head][c][m]
    __shared__ float bT[4 * 225];       // [head][rel_idx]
    __shared__ float o_s[64 * 33];      // attn output [n][32] (padded)
    __shared__ ULL   pw2[32 * 16];      // proj weight pairs [e][dpair]

    const int t    = threadIdx.x;
    const int b    = blockIdx.x >> 10;
    const int wrem = blockIdx.x & 1023;
    const int wy   = wrem >> 5;
    const int wx   = wrem & 31;
    const size_t gbase = (size_t)b * 65536 + (wy * 8) * 256 + wx * 8;

    for (int i = t; i < 64 * 96; i += 256) {
        int n = i / 96;
        int j = i - n * 96;
        size_t gtok = gbase + (n >> 3) * 256 + (n & 7);
        float v = g_qkv[gtok * 96 + j];
        int head = (j & 31) >> 3;
        int c    = j & 7;
        if (j < 32)      q_s[(head * 64 + n) * 8 + c] = v;
        else if (j < 64) kT[(head * 8 + c) * 64 + n]  = v;
        else             vT[(head * 8 + c) * 64 + n]  = v;
    }
    for (int i = t; i < 900; i += 256)
        bT[(i & 3) * 225 + (i >> 2)] = rpb[i];
    for (int i = t; i < 512; i += 256) {
        int e = i >> 4, dp = i & 15;
        unsigned ua = __float_as_uint(pw[(2 * dp)     * 32 + e]);
        unsigned ub = __float_as_uint(pw[(2 * dp + 1) * 32 + e]);
        pw2[i] = ((ULL)ub << 32) | ua;
    }
    __syncthreads();

    {   // scores + softmax + AV
        const int head = t >> 6;
        const int n    = t & 63;
        ULL qp[8];
        {
            const float4* qv = (const float4*)&q_s[(head * 64 + n) * 8];
            float4 a = qv[0], bq = qv[1];
            qp[0]=pack2(a.x,a.x);  qp[1]=pack2(a.y,a.y);  qp[2]=pack2(a.z,a.z);  qp[3]=pack2(a.w,a.w);
            qp[4]=pack2(bq.x,bq.x);qp[5]=pack2(bq.y,bq.y);qp[6]=pack2(bq.z,bq.z);qp[7]=pack2(bq.w,bq.w);
        }
        float s[64];
        const ULL* kt2 = (const ULL*)&kT[head * 512];
#pragma unroll 4
        for (int mp = 0; mp < 32; mp++) {
            ULL a = 0ULL;
#pragma unroll
            for (int c = 0; c < 8; c++) fma2(a, qp[c], kt2[c * 32 + mp]);
            float2 f = unpack2(a);
            s[2 * mp] = f.x; s[2 * mp + 1] = f.y;
        }
        const int ih = n >> 3, iw = n & 7;
        const float* bh = &bT[head * 225];
#pragma unroll 8
        for (int m = 0; m < 64; m++)
            s[m] += bh[(ih - (m >> 3) + 7) * 15 + (iw - (m & 7) + 7)];
        float mx = s[0];
#pragma unroll
        for (int m = 1; m < 64; m++) mx = fmaxf(mx, s[m]);
        float ssum = 0.f;
#pragma unroll
        for (int m = 0; m < 64; m++) { float e = __expf(s[m] - mx); s[m] = e; ssum += e; }
        float rinv = 1.f / ssum;
        ULL oa[8];
#pragma unroll
        for (int c = 0; c < 8; c++) oa[c] = 0ULL;
        const ULL* vt2 = (const ULL*)&vT[head * 512];
#pragma unroll 4
        for (int mp = 0; mp < 32; mp++) {
            ULL pp = pack2(s[2 * mp], s[2 * mp + 1]);
#pragma unroll
            for (int c = 0; c < 8; c++) fma2(oa[c], pp, vt2[c * 32 + mp]);
        }
#pragma unroll
        for (int c = 0; c < 8; c++) {
            float2 f = unpack2(oa[c]);
            o_s[n * 33 + head * 8 + c] = (f.x + f.y) * rinv;
        }
    }
    __syncthreads();

    {   // proj + residual -> g_x2
        const int n  = t >> 2;
        const int g4 = t & 3;
        ULL a2[4];
#pragma unroll
        for (int k = 0; k < 4; k++) a2[k] = 0ULL;
        const float* orow = &o_s[n * 33];
        for (int e = 0; e < 32; e++) {
            float oe = orow[e];
            ULL oe2 = pack2(oe, oe);
            const ULL* wr = &pw2[e * 16 + g4 * 4];
#pragma unroll
            for (int k = 0; k < 4; k++) fma2(a2[k], oe2, wr[k]);
        }
        size_t gtok = gbase + (n >> 3) * 256 + (n & 7);
#pragma unroll
        for (int k = 0; k < 4; k++) {
            int dp = g4 * 4 + k;
            float2 f = unpack2(a2[k]);
            float2 sc = *(const float2*)&g_x[gtok * 32 + 2 * dp];
            f.x += pb[2 * dp]     + sc.x;
            f.y += pb[2 * dp + 1] + sc.y;
            *(float2*)&g_x2[gtok * 32 + 2 * dp] = f;
        }
    }
}

// ============================================================================
// K4: LayerNorm + MLP (32 -> 128 -> 32, exact GELU) + residual, writing the
// final output in (B, D, H, W) layout.  One token per thread.
// ============================================================================
__global__ __launch_bounds__(256) void mlp_kernel(
    const float* __restrict__ g2, const float* __restrict__ b2,
    const float* __restrict__ f1b, const float* __restrict__ f1w,
    const float* __restrict__ f2w, const float* __restrict__ f2b,
    float* __restrict__ out)
{
    __shared__ ULL   w1[32 * 64];    // [d][jpair]
    __shared__ ULL   w2s[128 * 16];  // [j][dpair]
    __shared__ float sg[32], sbv[32], s1b[128], s2b[32];
    const int t = threadIdx.x;
    for (int i = t; i < 32 * 64; i += 256) {
        int d = i >> 6, jp = i & 63;
        unsigned ua = __float_as_uint(f1w[(2 * jp)     * 32 + d]);
        unsigned ub = __float_as_uint(f1w[(2 * jp + 1) * 32 + d]);
        w1[i] = ((ULL)ub << 32) | ua;
    }
    for (int i = t; i < 128 * 16; i += 256) {
        int j = i >> 4, dp = i & 15;
        unsigned ua = __float_as_uint(f2w[(2 * dp)     * 128 + j]);
        unsigned ub = __float_as_uint(f2w[(2 * dp + 1) * 128 + j]);
        w2s[i] = ((ULL)ub << 32) | ua;
    }
    if (t < 32)  { sg[t] = g2[t]; sbv[t] = b2[t]; s2b[t] = f2b[t]; }
    if (t < 128) s1b[t] = f1b[t];
    __syncthreads();

    const size_t tok = (size_t)blockIdx.x * 256 + t;
    float y[32];
    const float4* xp = (const float4*)&g_x2[tok * 32];
#pragma unroll
    for (int q = 0; q < 8; q++) {
        float4 f = xp[q];
        y[4*q] = f.x; y[4*q+1] = f.y; y[4*q+2] = f.z; y[4*q+3] = f.w;
    }
    float s = 0.f;
#pragma unroll
    for (int d = 0; d < 32; d++) s += y[d];
    float mu = s * (1.f / 32.f);
    float var = 0.f;
#pragma unroll
    for (int d = 0; d < 32; d++) { float dd = y[d] - mu; var += dd * dd; }
    float rs = rsqrtf(var * (1.f / 32.f) + 1e-5f);
#pragma unroll
    for (int d = 0; d < 32; d++) y[d] = (y[d] - mu) * rs * sg[d] + sbv[d];

    ULL out2[16];
#pragma unroll
    for (int p = 0; p < 16; p++) out2[p] = 0ULL;

    for (int jc = 0; jc < 4; jc++) {      // hidden processed in chunks of 32
        ULL h2[16];
#pragma unroll
        for (int p = 0; p < 16; p++) h2[p] = 0ULL;
        for (int d = 0; d < 32; d++) {
            ULL y2 = pack2(y[d], y[d]);
            const ULL* wr = &w1[d * 64 + jc * 16];
#pragma unroll
            for (int p = 0; p < 16; p++) fma2(h2[p], y2, wr[p]);
        }
#pragma unroll
        for (int p = 0; p < 16; p++) {
            int j = jc * 32 + 2 * p;
            float2 f = unpack2(h2[p]);
            float ga = gelu_exact(f.x + s1b[j]);
            float gb = gelu_exact(f.y + s1b[j + 1]);
            ULL a2  = pack2(ga, ga);
            ULL b2p = pack2(gb, gb);
            const ULL* wra = &w2s[j * 16];
            const ULL* wrb = &w2s[(j + 1) * 16];
#pragma unroll
            for (int dp = 0; dp < 16; dp++) {
                fma2(out2[dp], a2,  wra[dp]);
                fma2(out2[dp], b2p, wrb[dp]);
            }
        }
    }

    // residual (reload shortcut; L2-resident) + transpose to (B, D, H, W)
    const int bb = (int)(tok >> 16);
    const int l  = (int)(tok & 65535);
#pragma unroll
    for (int q = 0; q < 8; q++) {
        float4 f = xp[q];
        y[4*q] = f.x; y[4*q+1] = f.y; y[4*q+2] = f.z; y[4*q+3] = f.w;
    }
#pragma unroll
    for (int dp = 0; dp < 16; dp++) {
        float2 f = unpack2(out2[dp]);
        int d0 = 2 * dp;
        out[((size_t)(bb * 32 + d0)     * 65536) + l] = f.x + s2b[d0]     + y[d0];
        out[((size_t)(bb * 32 + d0 + 1) * 65536) + l] = f.y + s2b[d0 + 1] + y[d0 + 1];
    }
}

// ============================================================================
extern "C" void kernel_launch(void* const* d_in, const int* in_sizes, int n_in,
                              void* d_out, int out_size)
{
    const float* img  = (const float*)d_in[0];   // image_event_fea (4,128,256,256)
    const float* evt  = (const float*)d_in[1];   // event_fea
    const float* cw   = (const float*)d_in[2];   // conv1_w (16,128,3,3)
    const float* cb   = (const float*)d_in[3];   // conv1_b (16)
    const float* n1g  = (const float*)d_in[4];
    const float* n1b  = (const float*)d_in[5];
    const float* qw   = (const float*)d_in[6];   // qkv_w (96,32)
    const float* qb   = (const float*)d_in[7];
    const float* rpb  = (const float*)d_in[8];   // rpb_table (225,4)
    const float* pw   = (const float*)d_in[9];   // proj_w (32,32)
    const float* pb   = (const float*)d_in[10];
    const float* n2g  = (const float*)d_in[11];
    const float* n2b  = (const float*)d_in[12];
    const float* f1w  = (const float*)d_in[13];  // fc1_w (128,32)
    const float* f1b  = (const float*)d_in[14];
    const float* f2w  = (const float*)d_in[15];  // fc2_w (32,128)
    const float* f2b  = (const float*)d_in[16];
    float* out = (float*)d_out;

    dim3 gc(4, 16, 8);                       // x-tiles, y-tiles, B*2 images
    conv_kernel<<<gc, 256>>>(img, evt, cw, cb);
    lnqkv_kernel<<<1024, 256>>>(n1g, n1b, qw, qb);
    attn_kernel<<<4096, 256>>>(rpb, pw, pb);
    mlp_kernel<<<1024, 256>>>(n2g, n2b, f1b, f1w, f2w, f2b, out);
}